// round 4
// baseline (speedup 1.0000x reference)
#include <cuda_runtime.h>

typedef unsigned long long ull;

#define Bc 4
#define Tc 12
#define Nc 128
#define Hc 64
#define Pc 14
#define G4 256
#define EPW 8

// ---------------- scratch ----------------
__device__ float g_preB[Bc*Nc*Tc*G4];
__device__ float g_preG[Bc*Nc*Tc*G4];
__device__ float g_uI [Bc*Nc*Tc*G4];
__device__ float g_vJ [Bc*Nc*Tc*G4];
__device__ float g_beta [Bc*Nc*Pc];
__device__ float g_gamma[Bc*Nc*Pc];
__device__ float g_clg  [Bc*Nc*Pc*Nc];     // [(b*128+i)*14+p][j]
__device__ float g_WPb[G4*Hc], g_WPg[G4*Hc], g_WPc[G4*Hc];  // permuted Whh

// ---------------- helpers ----------------
__device__ __forceinline__ ull fma2(ull a, ull b, ull c) {
    ull d; asm("fma.rn.f32x2 %0, %1, %2, %3;" : "=l"(d) : "l"(a), "l"(b), "l"(c)); return d;
}
__device__ __forceinline__ ull add2(ull a, ull b) {
    ull d; asm("add.rn.f32x2 %0, %1, %2;" : "=l"(d) : "l"(a), "l"(b)); return d;
}
__device__ __forceinline__ float lo32(ull v){ return __int_as_float((int)(unsigned)v); }
__device__ __forceinline__ float hi32(ull v){ return __int_as_float((int)(unsigned)(v>>32)); }
__device__ __forceinline__ float sigf(float x){ return __fdividef(1.0f, 1.0f + __expf(-x)); }
__device__ __forceinline__ float tanhf_(float x){ return __fdividef(2.0f, 1.0f + __expf(-2.0f*x)) - 1.0f; }

// Permuted Whh layout: word idx = m*256 + ch*128 + l*4 + u,
// gate k = (ch*2 + (u>>1))*64 + 2*l + (u&1). Lane l reads words lane*4..+3
// (conflict-free LDS.128) giving 4 f32x2 pairs: gates (2l,2l+1) of groups 0..3.

__global__ void permute_whh_kernel(const float* __restrict__ bWhh,
                                   const float* __restrict__ gWhh,
                                   const float* __restrict__ cWhh) {
    int idx = blockIdx.x*256 + threadIdx.x;            // 0..16383
    int m = idx >> 8, rest = idx & 255;
    int ch = rest >> 7, l = (rest >> 2) & 31, u = rest & 3;
    int k = (ch*2 + (u >> 1))*64 + 2*l + (u & 1);
    g_WPb[idx] = bWhh[k*64 + m];
    g_WPg[idx] = gWhh[k*64 + m];
    g_WPc[idx] = cWhh[k*64 + m];
}

// ---------------- kernel 1: input projections ----------------
__global__ void precompute_kernel(const float* __restrict__ xs,
                                  const float* __restrict__ bWih, const float* __restrict__ bb,
                                  const float* __restrict__ gWih, const float* __restrict__ gb,
                                  const float* __restrict__ cWih, const float* __restrict__ cb) {
    int nt = blockIdx.x;                 // s*12+t, s=b*128+n
    int k  = threadIdx.x;                // 0..255
    int s = nt / Tc, t = nt % Tc;
    int b = s >> 7, n = s & 127;
    const float* xp = xs + (((size_t)(b*Tc + t)*Nc + n)*3);
    float x0 = xp[0], x1 = xp[1], x2 = xp[2];
    size_t o = (size_t)nt*G4 + k;
    g_preB[o] = bb[k] + bWih[k*3+0]*x0 + bWih[k*3+1]*x1 + bWih[k*3+2]*x2;
    g_preG[o] = gb[k] + gWih[k*3+0]*x0 + gWih[k*3+1]*x1 + gWih[k*3+2]*x2;
    g_uI[o]   = cb[k] + cWih[k*6+0]*x0 + cWih[k*6+1]*x1 + cWih[k*6+2]*x2;
    g_vJ[o]   =         cWih[k*6+3]*x0 + cWih[k*6+4]*x1 + cWih[k*6+5]*x2;
}

// ---------------- kernel 2: node LSTMs (1 seq/warp, y=0 beta, y=1 gamma) -------
__global__ void __launch_bounds__(256)
node_lstm_kernel(const float* __restrict__ bfW, const float* __restrict__ bfb,
                 const float* __restrict__ gfW, const float* __restrict__ gfb) {
    extern __shared__ float sm[];
    float*  wTp = sm;                          // 16384 floats
    float4* h4  = (float4*)(sm + 16384);       // [8 warps][32]

    const float* WP; const float* pre; const float* fW; const float* fb; float* outp;
    if (blockIdx.y == 0) { WP = g_WPb; pre = g_preB; fW = bfW; fb = bfb; outp = g_beta; }
    else                 { WP = g_WPg; pre = g_preG; fW = gfW; fb = gfb; outp = g_gamma; }

    for (int idx = threadIdx.x; idx < 16384; idx += 256) wTp[idx] = WP[idx];
    __syncthreads();

    int warp = threadIdx.x >> 5, lane = threadIdx.x & 31;
    int s = blockIdx.x*8 + warp;               // 0..511
    const float* prow = pre + (size_t)s*Tc*G4;
    float4* hrow = h4 + warp*32;

    float c0 = 0.f, c1 = 0.f;
    ull acc[4];
    for (int t = 0; t < Tc; ++t) {
        const float* pt = prow + t*G4;
#pragma unroll
        for (int g = 0; g < 4; ++g) acc[g] = *(const ull*)(pt + g*64 + 2*lane);
        if (t > 0) {
#pragma unroll 4
            for (int mp = 0; mp < 32; ++mp) {
                const float* wr = wTp + (2*mp)*256 + lane*4;
                ulonglong2 wa  = *(const ulonglong2*)(wr);
                ulonglong2 wb  = *(const ulonglong2*)(wr + 128);
                ulonglong2 wa1 = *(const ulonglong2*)(wr + 256);
                ulonglong2 wb1 = *(const ulonglong2*)(wr + 384);
                ulonglong2 hh  = *(const ulonglong2*)(hrow + mp);
                acc[0] = fma2(wa.x,  hh.x, acc[0]);
                acc[1] = fma2(wa.y,  hh.x, acc[1]);
                acc[2] = fma2(wb.x,  hh.x, acc[2]);
                acc[3] = fma2(wb.y,  hh.x, acc[3]);
                acc[0] = fma2(wa1.x, hh.y, acc[0]);
                acc[1] = fma2(wa1.y, hh.y, acc[1]);
                acc[2] = fma2(wb1.x, hh.y, acc[2]);
                acc[3] = fma2(wb1.y, hh.y, acc[3]);
            }
        }
        __syncwarp();
        float i0 = sigf(lo32(acc[0])), i1 = sigf(hi32(acc[0]));
        float f0 = sigf(lo32(acc[1])), f1 = sigf(hi32(acc[1]));
        float q0 = tanhf_(lo32(acc[2])), q1 = tanhf_(hi32(acc[2]));
        float o0 = sigf(lo32(acc[3])), o1 = sigf(hi32(acc[3]));
        c0 = f0*c0 + i0*q0;  c1 = f1*c1 + i1*q1;
        float h0 = o0*tanhf_(c0), h1 = o1*tanhf_(c1);
        hrow[lane] = make_float4(h0, h0, h1, h1);
        __syncwarp();
    }
    if (lane < Pc) {
        const float*  wr = fW + lane*Hc;
        const float2* hv = (const float2*)hrow;
        float a = fb[lane];
#pragma unroll
        for (int m = 0; m < Hc; ++m) a += wr[m]*hv[m].x;
        outp[s*Pc + lane] = sigf(a);
    }
}

// ---------------- kernel 3: edge LSTM (8 edges/warp) ----------------
__global__ void __launch_bounds__(256, 2)
edge_lstm_kernel(const float* __restrict__ cfW, const float* __restrict__ cfb) {
    extern __shared__ float sm[];
    float*  wTp = sm;                          // 64KB
    float4* h4  = (float4*)(sm + 16384);       // 64 edges * 32 float4 = 32KB

    for (int idx = threadIdx.x; idx < 16384; idx += 256) wTp[idx] = g_WPc[idx];
    __syncthreads();

    int warp = threadIdx.x >> 5, lane = threadIdx.x & 31;
    int ebase = (blockIdx.x*8 + warp)*EPW;     // same (b,i), j0..j0+7
    int b  = ebase >> 14;
    int i  = (ebase >> 7) & 127;
    int j0 = ebase & 127;
    const float* urow  = g_uI + (size_t)((b << 7) | i )*Tc*G4;
    const float* vrow0 = g_vJ + (size_t)((b << 7) | j0)*Tc*G4;
    float4* hbase = h4 + warp*EPW*32;

    float c0[EPW], c1[EPW];
#pragma unroll
    for (int e = 0; e < EPW; ++e) { c0[e] = 0.f; c1[e] = 0.f; }

    ull acc[EPW][4];
    for (int t = 0; t < Tc; ++t) {
        const float* ut = urow  + t*G4;
        const float* vt = vrow0 + t*G4;
#pragma unroll
        for (int g = 0; g < 4; ++g) {
            ull u2 = *(const ull*)(ut + g*64 + 2*lane);
#pragma unroll
            for (int e = 0; e < EPW; ++e) {
                ull v2 = *(const ull*)(vt + e*(Tc*G4) + g*64 + 2*lane);
                acc[e][g] = add2(u2, v2);
            }
        }
        if (t > 0) {
#pragma unroll 2
            for (int mp = 0; mp < 32; ++mp) {
                const float* wr = wTp + (2*mp)*256 + lane*4;
                ulonglong2 wa  = *(const ulonglong2*)(wr);
                ulonglong2 wb  = *(const ulonglong2*)(wr + 128);
                ulonglong2 wa1 = *(const ulonglong2*)(wr + 256);
                ulonglong2 wb1 = *(const ulonglong2*)(wr + 384);
#pragma unroll
                for (int e = 0; e < EPW; ++e) {
                    ulonglong2 hh = *(const ulonglong2*)(hbase + e*32 + mp);
                    acc[e][0] = fma2(wa.x,  hh.x, acc[e][0]);
                    acc[e][1] = fma2(wa.y,  hh.x, acc[e][1]);
                    acc[e][2] = fma2(wb.x,  hh.x, acc[e][2]);
                    acc[e][3] = fma2(wb.y,  hh.x, acc[e][3]);
                    acc[e][0] = fma2(wa1.x, hh.y, acc[e][0]);
                    acc[e][1] = fma2(wa1.y, hh.y, acc[e][1]);
                    acc[e][2] = fma2(wb1.x, hh.y, acc[e][2]);
                    acc[e][3] = fma2(wb1.y, hh.y, acc[e][3]);
                }
            }
        }
        __syncwarp();
#pragma unroll
        for (int e = 0; e < EPW; ++e) {
            float i0 = sigf(lo32(acc[e][0])), i1 = sigf(hi32(acc[e][0]));
            float f0 = sigf(lo32(acc[e][1])), f1 = sigf(hi32(acc[e][1]));
            float q0 = tanhf_(lo32(acc[e][2])), q1 = tanhf_(hi32(acc[e][2]));
            float o0 = sigf(lo32(acc[e][3])), o1 = sigf(hi32(acc[e][3]));
            c0[e] = f0*c0[e] + i0*q0;
            c1[e] = f1*c1[e] + i1*q1;
            float h0 = o0*tanhf_(c0[e]);
            float h1 = o1*tanhf_(c1[e]);
            hbase[e*32 + lane] = make_float4(h0, h0, h1, h1);
        }
        __syncwarp();
    }
#pragma unroll 1
    for (int e = 0; e < EPW; ++e) {
        if (lane < Pc) {
            const float*  wr = cfW + lane*Hc;
            const float2* hv = (const float2*)(hbase + e*32);
            float a = cfb[lane];
#pragma unroll
            for (int m = 0; m < Hc; ++m) a += wr[m]*hv[m].x;
            g_clg[(size_t)(((b*Nc + i)*Pc + lane))*Nc + (j0 + e)] = sigf(a);
        }
    }
}

// ---------------- kernel 4: softmax over j + write epi ----------------
__global__ void softmax_kernel(float* __restrict__ out) {
    int row  = blockIdx.x*4 + (threadIdx.x >> 5);   // (b*128+i)*14+p, 0..7167
    int lane = threadIdx.x & 31;
    const float* src = g_clg + (size_t)row*Nc;
    float v[4]; float s = 0.f;
#pragma unroll
    for (int q = 0; q < 4; ++q) { v[q] = __expf(src[lane + 32*q]); s += v[q]; }
#pragma unroll
    for (int off = 16; off; off >>= 1) s += __shfl_xor_sync(0xffffffffu, s, off);
    float inv = __fdividef(1.0f, s);
    int bi = row / Pc, p = row % Pc;
    int b = bi >> 7, i = bi & 127;
    float* e = out + 7168 + ((size_t)((b*Pc + p)*Nc + i))*130;
    if (lane == 0) { e[0] = g_beta[row]; e[1] = g_gamma[row]; }
#pragma unroll
    for (int q = 0; q < 4; ++q) e[2 + lane + 32*q] = v[q]*inv;
}

// ---------------- kernel 5: SIR scan ----------------
__global__ void sir_kernel(const float* __restrict__ x, float* __restrict__ out) {
    int b = blockIdx.x;          // 0..3
    int i = threadIdx.x;         // 0..127
    __shared__ float Ish[Nc];
    const float* xp = x + (((size_t)(b*Tc + (Tc-1))*Nc) + i)*3;
    float S = xp[0], I = xp[1], R = xp[2];
    Ish[i] = I; __syncthreads();
    for (int p = 0; p < Pc; ++p) {
        const float* e = out + 7168 + ((size_t)((b*Pc + p)*Nc + i))*130;
        float beta = e[0], gamma = e[1];
        float inf = 0.f;
#pragma unroll 4
        for (int j = 0; j < Nc; ++j) inf += e[2 + j]*Ish[j];
        float Ntot = fmaxf(S + I + R, 1e-8f);
        float dS = -beta*S/Ntot*inf;
        float dI = -dS - gamma*I;
        float dR = gamma*I;
        float St = fmaxf(S + dS, 0.f);
        float It = fmaxf(I + dI, 0.f);
        float Rt = fmaxf(R + dR, 0.f);
        float sc = Ntot / fmaxf(St + It + Rt, 1e-8f);
        float Inew = fmaxf(-dS, 0.f);
        St *= sc; It *= sc; Rt *= sc;
        size_t idx = (size_t)(b*Pc + p)*Nc + i;
        out[idx] = It;                                      // o1: I_t*scale
        float* o3 = out + 7168 + 931840 + idx*3;            // o3: S,I,R scaled
        o3[0] = St; o3[1] = It; o3[2] = Rt;
        out[7168 + 931840 + 21504 + idx] = Inew;            // o4: I_new
        __syncthreads();
        S = St; I = It; R = Rt;
        Ish[i] = I;
        __syncthreads();
    }
}

extern "C" void kernel_launch(void* const* d_in, const int* in_sizes, int n_in,
                              void* d_out, int out_size) {
    const float* x_s  = (const float*)d_in[0];
    const float* x    = (const float*)d_in[1];
    const float* bWih = (const float*)d_in[2];
    const float* bWhh = (const float*)d_in[3];
    const float* bb   = (const float*)d_in[4];
    const float* bfW  = (const float*)d_in[5];
    const float* bfb  = (const float*)d_in[6];
    const float* gWih = (const float*)d_in[7];
    const float* gWhh = (const float*)d_in[8];
    const float* gb   = (const float*)d_in[9];
    const float* gfW  = (const float*)d_in[10];
    const float* gfb  = (const float*)d_in[11];
    const float* cWih = (const float*)d_in[12];
    const float* cWhh = (const float*)d_in[13];
    const float* cb   = (const float*)d_in[14];
    const float* cfW  = (const float*)d_in[15];
    const float* cfb  = (const float*)d_in[16];
    float* out = (float*)d_out;

    static bool attr_done = false;
    if (!attr_done) {
        cudaFuncSetAttribute(node_lstm_kernel, cudaFuncAttributeMaxDynamicSharedMemorySize, 69632);
        cudaFuncSetAttribute(edge_lstm_kernel, cudaFuncAttributeMaxDynamicSharedMemorySize, 98304);
        attr_done = true;
    }

    permute_whh_kernel<<<64, 256>>>(bWhh, gWhh, cWhh);
    precompute_kernel<<<Bc*Nc*Tc, 256>>>(x_s, bWih, bb, gWih, gb, cWih, cb);
    node_lstm_kernel<<<dim3(64, 2), 256, 69632>>>(bfW, bfb, gfW, gfb);
    edge_lstm_kernel<<<1024, 256, 98304>>>(cfW, cfb);
    softmax_kernel<<<1792, 128>>>(out);
    sir_kernel<<<Bc, Nc>>>(x, out);
}